// round 6
// baseline (speedup 1.0000x reference)
#include <cuda_runtime.h>

// Problem constants (fixed by the reference setup_inputs)
#define BB 4
#define TT 4096
#define CCH 1024
#define HH 64

#define NUNITS 544      // sum over i of ceil((i+1)/4), i in [0,64)

// Projected q,k,v (two buffer sets for split-K projection; merged before attn)
__device__ float g_q [BB * TT * HH];
__device__ float g_k [BB * TT * HH];
__device__ float g_v [BB * TT * HH];
__device__ float g_q2[BB * TT * HH];
__device__ float g_k2[BB * TT * HH];
__device__ float g_v2[BB * TT * HH];

// Split-KV partials: per unit a [64 x 64] unnormalized O tile + row stats
__device__ float gOp[(size_t)BB * NUNITS * 64 * 64];   // ~35.7 MB
__device__ float gMp[BB * NUNITS * 64];
__device__ float gLp[BB * NUNITS * 64];

// ---------------------------------------------------------------------------
// Kernel 1: fused QKV projection, split-K (blockIdx.y selects K half + buffer)
// One block computes a [64 x 192] output tile over 512 of the 1024 K values.
// ---------------------------------------------------------------------------
__global__ __launch_bounds__(256)
void qkv_proj(const float* __restrict__ x, const float* __restrict__ Wq,
              const float* __restrict__ Wk, const float* __restrict__ Wv)
{
    __shared__ float xs[64 * 32];    // x chunk  [64 rows][32 k]
    __shared__ float ws[32 * 192];   // W chunk  [32 k][192 cols]

    const int tid  = threadIdx.x;
    const int row0 = blockIdx.x * 64;
    const int koff = blockIdx.y * (CCH / 2);
    const int ty   = tid >> 4;
    const int tx   = tid & 15;

    float* outq = blockIdx.y ? g_q2 : g_q;
    float* outk = blockIdx.y ? g_k2 : g_k;
    float* outv = blockIdx.y ? g_v2 : g_v;

    float acc[4][12];
#pragma unroll
    for (int r = 0; r < 4; r++)
#pragma unroll
        for (int j = 0; j < 12; j++) acc[r][j] = 0.f;

    for (int kk = koff; kk < koff + CCH / 2; kk += 32) {
        __syncthreads();
#pragma unroll
        for (int l = 0; l < 2; l++) {
            int idx = tid + l * 256;
            int r = idx >> 3, c4 = idx & 7;
            *(float4*)&xs[r * 32 + c4 * 4] =
                *(const float4*)&x[(size_t)(row0 + r) * CCH + kk + c4 * 4];
        }
#pragma unroll
        for (int l = 0; l < 6; l++) {
            int idx = tid + l * 256;
            int kr = idx / 48;
            int c  = (idx % 48) * 4;
            const float* Wsrc = (c < 64) ? Wq : ((c < 128) ? Wk : Wv);
            *(float4*)&ws[kr * 192 + c] =
                *(const float4*)&Wsrc[(size_t)(kk + kr) * HH + (c & 63)];
        }
        __syncthreads();

#pragma unroll 8
        for (int k = 0; k < 32; k++) {
            float a[4];
#pragma unroll
            for (int r = 0; r < 4; r++) a[r] = xs[(ty * 4 + r) * 32 + k];
            float4 b0 = *(float4*)&ws[k * 192 + tx * 12];
            float4 b1 = *(float4*)&ws[k * 192 + tx * 12 + 4];
            float4 b2 = *(float4*)&ws[k * 192 + tx * 12 + 8];
            float bb[12] = {b0.x, b0.y, b0.z, b0.w,
                            b1.x, b1.y, b1.z, b1.w,
                            b2.x, b2.y, b2.z, b2.w};
#pragma unroll
            for (int r = 0; r < 4; r++)
#pragma unroll
                for (int j = 0; j < 12; j++)
                    acc[r][j] = fmaf(a[r], bb[j], acc[r][j]);
        }
    }

#pragma unroll
    for (int r = 0; r < 4; r++) {
        int row = row0 + ty * 4 + r;
#pragma unroll
        for (int j = 0; j < 12; j++) {
            int c = tx * 12 + j;
            float* dst = (c < 64) ? outq : ((c < 128) ? outk : outv);
            dst[(size_t)row * HH + (c & 63)] = acc[r][j];
        }
    }
}

// ---------------------------------------------------------------------------
// Kernel 2: merge the two K-half buffers (g_* += g_*2)
// ---------------------------------------------------------------------------
__global__ __launch_bounds__(256)
void sum_halves()
{
    const int idx = blockIdx.x * 256 + threadIdx.x;   // float4 index, 0..262143
    float4* a; const float4* b;
    if (blockIdx.y == 0)      { a = (float4*)g_q; b = (const float4*)g_q2; }
    else if (blockIdx.y == 1) { a = (float4*)g_k; b = (const float4*)g_k2; }
    else                      { a = (float4*)g_v; b = (const float4*)g_v2; }
    float4 va = a[idx], vb = b[idx];
    va.x += vb.x; va.y += vb.y; va.z += vb.z; va.w += vb.w;
    a[idx] = va;
}

// ---------------------------------------------------------------------------
// Kernel 3: split-KV causal flash attention partial pass, fp32.
// Work unit = (batch b, query tile i, KV chunk u of <=4 KV tiles).
// Unit layout over z in [0,544): group g = i/4, units-per-i = g+1,
//   z = 2g(g+1) + (i%4)(g+1) + u.
// Writes unnormalized O tile + per-row (m, l) to scratch.
// ---------------------------------------------------------------------------
__global__ __launch_bounds__(256)
void attn_part()
{
    __shared__ float Qs[64 * 64];
    __shared__ float KtPs[64 * 64];
    __shared__ float Vs[64 * 64];

    const int tid = threadIdx.x;
    const int ty  = tid >> 4;
    const int tx  = tid & 15;
    const int z   = (NUNITS - 1) - (int)blockIdx.x;  // heavy (4-tile) units first
    const int b   = blockIdx.y;

    // decode z -> (i, u)
    int g = 0;
    while (2 * (g + 1) * (g + 2) <= z) g++;
    const int off = z - 2 * g * (g + 1);
    const int i   = 4 * g + off / (g + 1);
    const int u   = off % (g + 1);
    const int j0  = u * 4;
    const int j1  = (u * 4 + 4 < i + 1) ? (u * 4 + 4) : (i + 1);

    const float* qg = g_q + (size_t)b * TT * HH;
    const float* kg = g_k + (size_t)b * TT * HH;
    const float* vg = g_v + (size_t)b * TT * HH;

    // load Q tile [64][64]
#pragma unroll
    for (int l = 0; l < 4; l++) {
        int idx = tid + l * 256;
        int r = idx >> 4, c4 = idx & 15;
        *(float4*)&Qs[r * 64 + c4 * 4] =
            *(const float4*)&qg[(size_t)(i * 64 + r) * HH + c4 * 4];
    }

    float accO[4][4];
    float mrun[4], lrun[4];
#pragma unroll
    for (int r = 0; r < 4; r++) {
        mrun[r] = -1e30f;
        lrun[r] = 0.f;
#pragma unroll
        for (int c = 0; c < 4; c++) accO[r][c] = 0.f;
    }

    for (int j = j0; j < j1; j++) {
        const int jc0 = j * 64;
        __syncthreads();   // previous tile's reads done; Q load visible

        // K tile, transposed into KtPs[h*64 + c]
        {
            int cbase = tid >> 4;
            int h4    = tid & 15;
#pragma unroll
            for (int l = 0; l < 4; l++) {
                int c = cbase + 16 * l;
                float4 kv = *(const float4*)&kg[(size_t)(jc0 + c) * HH + h4 * 4];
                KtPs[(h4 * 4 + 0) * 64 + c] = kv.x;
                KtPs[(h4 * 4 + 1) * 64 + c] = kv.y;
                KtPs[(h4 * 4 + 2) * 64 + c] = kv.z;
                KtPs[(h4 * 4 + 3) * 64 + c] = kv.w;
            }
        }
        // V tile [c][h]
#pragma unroll
        for (int l = 0; l < 4; l++) {
            int idx = tid + l * 256;
            int r = idx >> 4, c4 = idx & 15;
            *(float4*)&Vs[r * 64 + c4 * 4] =
                *(const float4*)&vg[(size_t)(jc0 + r) * HH + c4 * 4];
        }
        __syncthreads();

        // ---- S = Q K^T ----
        float accS[4][4];
#pragma unroll
        for (int r = 0; r < 4; r++)
#pragma unroll
            for (int c = 0; c < 4; c++) accS[r][c] = 0.f;

#pragma unroll 4
        for (int h = 0; h < 64; h += 4) {
            float4 k0 = *(float4*)&KtPs[(h + 0) * 64 + tx * 4];
            float4 k1 = *(float4*)&KtPs[(h + 1) * 64 + tx * 4];
            float4 k2 = *(float4*)&KtPs[(h + 2) * 64 + tx * 4];
            float4 k3 = *(float4*)&KtPs[(h + 3) * 64 + tx * 4];
#pragma unroll
            for (int r = 0; r < 4; r++) {
                float4 qv = *(float4*)&Qs[(ty * 4 + r) * 64 + h];
                accS[r][0] = fmaf(qv.x, k0.x, accS[r][0]);
                accS[r][1] = fmaf(qv.x, k0.y, accS[r][1]);
                accS[r][2] = fmaf(qv.x, k0.z, accS[r][2]);
                accS[r][3] = fmaf(qv.x, k0.w, accS[r][3]);
                accS[r][0] = fmaf(qv.y, k1.x, accS[r][0]);
                accS[r][1] = fmaf(qv.y, k1.y, accS[r][1]);
                accS[r][2] = fmaf(qv.y, k1.z, accS[r][2]);
                accS[r][3] = fmaf(qv.y, k1.w, accS[r][3]);
                accS[r][0] = fmaf(qv.z, k2.x, accS[r][0]);
                accS[r][1] = fmaf(qv.z, k2.y, accS[r][1]);
                accS[r][2] = fmaf(qv.z, k2.z, accS[r][2]);
                accS[r][3] = fmaf(qv.z, k2.w, accS[r][3]);
                accS[r][0] = fmaf(qv.w, k3.x, accS[r][0]);
                accS[r][1] = fmaf(qv.w, k3.y, accS[r][1]);
                accS[r][2] = fmaf(qv.w, k3.z, accS[r][2]);
                accS[r][3] = fmaf(qv.w, k3.w, accS[r][3]);
            }
        }

        // ---- online softmax ----  scale = 1/sqrt(C) = 1/32
        const bool diag = (j == i);
        float p[4][4];
#pragma unroll
        for (int r = 0; r < 4; r++) {
            const int grow = i * 64 + ty * 4 + r;
            float mloc = -1e30f;
#pragma unroll
            for (int c = 0; c < 4; c++) {
                float s = accS[r][c] * 0.03125f;
                if (diag && (jc0 + tx * 4 + c > grow)) s = -1e30f;
                accS[r][c] = s;
                mloc = fmaxf(mloc, s);
            }
            mloc = fmaxf(mloc, __shfl_xor_sync(0xffffffffu, mloc, 8));
            mloc = fmaxf(mloc, __shfl_xor_sync(0xffffffffu, mloc, 4));
            mloc = fmaxf(mloc, __shfl_xor_sync(0xffffffffu, mloc, 2));
            mloc = fmaxf(mloc, __shfl_xor_sync(0xffffffffu, mloc, 1));
            float mnew  = fmaxf(mrun[r], mloc);
            float alpha = __expf(mrun[r] - mnew);
            mrun[r] = mnew;
            float psum = 0.f;
#pragma unroll
            for (int c = 0; c < 4; c++) {
                float pe = __expf(accS[r][c] - mnew);
                p[r][c] = pe;
                psum += pe;
            }
            psum += __shfl_xor_sync(0xffffffffu, psum, 8);
            psum += __shfl_xor_sync(0xffffffffu, psum, 4);
            psum += __shfl_xor_sync(0xffffffffu, psum, 2);
            psum += __shfl_xor_sync(0xffffffffu, psum, 1);
            lrun[r] = lrun[r] * alpha + psum;
#pragma unroll
            for (int c = 0; c < 4; c++) accO[r][c] *= alpha;
        }

        __syncthreads();   // all S-phase reads of KtPs done
#pragma unroll
        for (int r = 0; r < 4; r++) {
            float4 pv = make_float4(p[r][0], p[r][1], p[r][2], p[r][3]);
            *(float4*)&KtPs[(ty * 4 + r) * 64 + tx * 4] = pv;
        }
        __syncthreads();

        // ---- O += P V ----
#pragma unroll 4
        for (int c = 0; c < 64; c += 4) {
            float4 v0 = *(float4*)&Vs[(c + 0) * 64 + tx * 4];
            float4 v1 = *(float4*)&Vs[(c + 1) * 64 + tx * 4];
            float4 v2 = *(float4*)&Vs[(c + 2) * 64 + tx * 4];
            float4 v3 = *(float4*)&Vs[(c + 3) * 64 + tx * 4];
#pragma unroll
            for (int r = 0; r < 4; r++) {
                float4 pv = *(float4*)&KtPs[(ty * 4 + r) * 64 + c];
                accO[r][0] = fmaf(pv.x, v0.x, accO[r][0]);
                accO[r][1] = fmaf(pv.x, v0.y, accO[r][1]);
                accO[r][2] = fmaf(pv.x, v0.z, accO[r][2]);
                accO[r][3] = fmaf(pv.x, v0.w, accO[r][3]);
                accO[r][0] = fmaf(pv.y, v1.x, accO[r][0]);
                accO[r][1] = fmaf(pv.y, v1.y, accO[r][1]);
                accO[r][2] = fmaf(pv.y, v1.z, accO[r][2]);
                accO[r][3] = fmaf(pv.y, v1.w, accO[r][3]);
                accO[r][0] = fmaf(pv.z, v2.x, accO[r][0]);
                accO[r][1] = fmaf(pv.z, v2.y, accO[r][1]);
                accO[r][2] = fmaf(pv.z, v2.z, accO[r][2]);
                accO[r][3] = fmaf(pv.z, v2.w, accO[r][3]);
                accO[r][0] = fmaf(pv.w, v3.x, accO[r][0]);
                accO[r][1] = fmaf(pv.w, v3.y, accO[r][1]);
                accO[r][2] = fmaf(pv.w, v3.z, accO[r][2]);
                accO[r][3] = fmaf(pv.w, v3.w, accO[r][3]);
            }
        }
    }

    // write partial results (unnormalized O + row stats)
    const size_t zu = (size_t)b * NUNITS + z;
#pragma unroll
    for (int r = 0; r < 4; r++) {
        float4 o = make_float4(accO[r][0], accO[r][1], accO[r][2], accO[r][3]);
        *(float4*)&gOp[(zu * 64 + ty * 4 + r) * 64 + tx * 4] = o;
    }
    if (tx == 0) {
#pragma unroll
        for (int r = 0; r < 4; r++) {
            gMp[zu * 64 + ty * 4 + r] = mrun[r];
            gLp[zu * 64 + ty * 4 + r] = lrun[r];
        }
    }
}

// ---------------------------------------------------------------------------
// Kernel 4: combine split-KV partials -> out [B,T,H]
// Block = (q tile i, batch b). 256 threads: 4 threads per row, 16 h each.
// ---------------------------------------------------------------------------
__global__ __launch_bounds__(256)
void combine(float* __restrict__ out)
{
    const int i  = blockIdx.x;
    const int b  = blockIdx.y;
    const int g  = i >> 2;
    const int nu = g + 1;
    const int zb = 2 * g * (g + 1) + (i & 3) * (g + 1);
    const int tid = threadIdx.x;
    const int r   = tid >> 2;
    const int hb  = (tid & 3) * 16;
    const size_t ub = (size_t)b * NUNITS + zb;

    float mmax = -1e30f;
    for (int u = 0; u < nu; u++)
        mmax = fmaxf(mmax, gMp[(ub + u) * 64 + r]);

    float acc[16];
#pragma unroll
    for (int t = 0; t < 16; t++) acc[t] = 0.f;
    float L = 0.f;

    for (int u = 0; u < nu; u++) {
        const float w = __expf(gMp[(ub + u) * 64 + r] - mmax);
        L += w * gLp[(ub + u) * 64 + r];
        const float4* src = (const float4*)&gOp[((ub + u) * 64 + r) * 64 + hb];
#pragma unroll
        for (int t = 0; t < 4; t++) {
            float4 s = src[t];
            acc[t * 4 + 0] += w * s.x;
            acc[t * 4 + 1] += w * s.y;
            acc[t * 4 + 2] += w * s.z;
            acc[t * 4 + 3] += w * s.w;
        }
    }

    const float inv = 1.f / L;
    float4* dst = (float4*)&out[((size_t)(b * TT + i * 64 + r)) * HH + hb];
#pragma unroll
    for (int t = 0; t < 4; t++)
        dst[t] = make_float4(acc[t * 4 + 0] * inv, acc[t * 4 + 1] * inv,
                             acc[t * 4 + 2] * inv, acc[t * 4 + 3] * inv);
}

// ---------------------------------------------------------------------------
extern "C" void kernel_launch(void* const* d_in, const int* in_sizes, int n_in,
                              void* d_out, int out_size)
{
    (void)in_sizes; (void)n_in; (void)out_size;
    const float* x  = (const float*)d_in[0];
    const float* Wq = (const float*)d_in[1];
    const float* Wk = (const float*)d_in[2];
    const float* Wv = (const float*)d_in[3];
    float* out = (float*)d_out;

    qkv_proj<<<dim3((BB * TT) / 64, 2), 256>>>(x, Wq, Wk, Wv);
    sum_halves<<<dim3((BB * TT * HH / 4) / 256, 3), 256>>>();
    attn_part<<<dim3(NUNITS, BB), 256>>>();
    combine<<<dim3(TT / 64, BB), 256>>>(out);
}

// round 8
// speedup vs baseline: 1.7144x; 1.7144x over previous
#include <cuda_runtime.h>

// Problem constants (fixed by the reference setup_inputs)
#define BB 4
#define TT 4096
#define CCH 1024
#define HH 64

#define NUNITS 544      // sum over i of ceil((i+1)/4), i in [0,64)

// Projected q,k,v
__device__ float g_q[BB * TT * HH];
__device__ float g_k[BB * TT * HH];
__device__ float g_v[BB * TT * HH];

// Split-KV partials: per unit a [64 x 64] unnormalized O tile + row stats
__device__ float gOp[(size_t)BB * NUNITS * 64 * 64];   // ~35.7 MB
__device__ float gMp[BB * NUNITS * 64];
__device__ float gLp[BB * NUNITS * 64];

// ---------------------------------------------------------------------------
// Kernel 1: fused QKV projection (round-4 version; ~90% of fp32 FFMA peak).
// One block computes a [64 x 192] output tile (192 = 3*H spanning q|k|v),
// looping over K=1024 in chunks of 32 held in smem.
// ---------------------------------------------------------------------------
__global__ __launch_bounds__(256)
void qkv_proj(const float* __restrict__ x, const float* __restrict__ Wq,
              const float* __restrict__ Wk, const float* __restrict__ Wv)
{
    __shared__ float xs[64 * 32];    // x chunk  [64 rows][32 k]
    __shared__ float ws[32 * 192];   // W chunk  [32 k][192 cols]

    const int tid  = threadIdx.x;
    const int row0 = blockIdx.x * 64;
    const int ty   = tid >> 4;
    const int tx   = tid & 15;

    float acc[4][12];
#pragma unroll
    for (int r = 0; r < 4; r++)
#pragma unroll
        for (int j = 0; j < 12; j++) acc[r][j] = 0.f;

    for (int kk = 0; kk < CCH; kk += 32) {
        __syncthreads();
#pragma unroll
        for (int l = 0; l < 2; l++) {
            int idx = tid + l * 256;
            int r = idx >> 3, c4 = idx & 7;
            *(float4*)&xs[r * 32 + c4 * 4] =
                *(const float4*)&x[(size_t)(row0 + r) * CCH + kk + c4 * 4];
        }
#pragma unroll
        for (int l = 0; l < 6; l++) {
            int idx = tid + l * 256;
            int kr = idx / 48;
            int c  = (idx % 48) * 4;
            const float* Wsrc = (c < 64) ? Wq : ((c < 128) ? Wk : Wv);
            *(float4*)&ws[kr * 192 + c] =
                *(const float4*)&Wsrc[(size_t)(kk + kr) * HH + (c & 63)];
        }
        __syncthreads();

#pragma unroll 8
        for (int k = 0; k < 32; k++) {
            float a[4];
#pragma unroll
            for (int r = 0; r < 4; r++) a[r] = xs[(ty * 4 + r) * 32 + k];
            float4 b0 = *(float4*)&ws[k * 192 + tx * 12];
            float4 b1 = *(float4*)&ws[k * 192 + tx * 12 + 4];
            float4 b2 = *(float4*)&ws[k * 192 + tx * 12 + 8];
            float bb[12] = {b0.x, b0.y, b0.z, b0.w,
                            b1.x, b1.y, b1.z, b1.w,
                            b2.x, b2.y, b2.z, b2.w};
#pragma unroll
            for (int r = 0; r < 4; r++)
#pragma unroll
                for (int j = 0; j < 12; j++)
                    acc[r][j] = fmaf(a[r], bb[j], acc[r][j]);
        }
    }

#pragma unroll
    for (int r = 0; r < 4; r++) {
        int row = row0 + ty * 4 + r;
#pragma unroll
        for (int j = 0; j < 12; j++) {
            int c = tx * 12 + j;
            float* dst = (c < 64) ? g_q : ((c < 128) ? g_k : g_v);
            dst[(size_t)row * HH + (c & 63)] = acc[r][j];
        }
    }
}

// ---------------------------------------------------------------------------
// Kernel 2: split-KV causal flash attention partial pass, fp32.
// Work unit = (batch b, query tile i, KV chunk u of <=4 KV tiles).
// z = 2g(g+1) + (i%4)(g+1) + u, g = i/4.
// Transpose store is bank-conflict-free (lane -> 16 consecutive columns,
// 2 h-rows per warp: 16 banks 2-way instead of 2 banks 16-way).
// K prefetched into regs before the tile barrier; V's STS deferred past the
// S GEMM so its LDG latency hides under compute.
// ---------------------------------------------------------------------------
__global__ __launch_bounds__(256, 3)
void attn_part()
{
    __shared__ float Qs[64 * 64];
    __shared__ float KtPs[64 * 64];
    __shared__ float Vs[64 * 64];

    const int tid = threadIdx.x;
    const int ty  = tid >> 4;
    const int tx  = tid & 15;
    const int z   = (NUNITS - 1) - (int)blockIdx.x;  // heavy (4-tile) units first
    const int b   = blockIdx.y;

    // decode z -> (i, u)
    int g = 0;
    while (2 * (g + 1) * (g + 2) <= z) g++;
    const int off = z - 2 * g * (g + 1);
    const int i   = 4 * g + off / (g + 1);
    const int u   = off % (g + 1);
    const int j0  = u * 4;
    const int j1  = (u * 4 + 4 < i + 1) ? (u * 4 + 4) : (i + 1);

    const float* qg = g_q + (size_t)b * TT * HH;
    const float* kg = g_k + (size_t)b * TT * HH;
    const float* vg = g_v + (size_t)b * TT * HH;

    // transpose-loader lane mapping: c16 = column group, h4 = float4 along h
    const int c16 = tid & 15;   // 16 consecutive columns per quarter-warp
    const int h4  = tid >> 4;   // 0..15

    // load Q tile [64][64]
#pragma unroll
    for (int l = 0; l < 4; l++) {
        int idx = tid + l * 256;
        int r = idx >> 4, c4 = idx & 15;
        *(float4*)&Qs[r * 64 + c4 * 4] =
            *(const float4*)&qg[(size_t)(i * 64 + r) * HH + c4 * 4];
    }

    float accO[4][4];
    float mrun[4], lrun[4];
#pragma unroll
    for (int r = 0; r < 4; r++) {
        mrun[r] = -1e30f;
        lrun[r] = 0.f;
#pragma unroll
        for (int c = 0; c < 4; c++) accO[r][c] = 0.f;
    }

    for (int j = j0; j < j1; j++) {
        const int jc0 = j * 64;

        // prefetch K tile into registers (overlaps previous tile's PV)
        float4 kv[4];
#pragma unroll
        for (int l = 0; l < 4; l++)
            kv[l] = *(const float4*)&kg[(size_t)(jc0 + c16 + 16 * l) * HH + h4 * 4];

        __syncthreads();   // previous tile's smem reads complete

        // conflict-free transposed store: KtPs[h][c]
#pragma unroll
        for (int l = 0; l < 4; l++) {
            const int c = c16 + 16 * l;
            KtPs[(h4 * 4 + 0) * 64 + c] = kv[l].x;
            KtPs[(h4 * 4 + 1) * 64 + c] = kv[l].y;
            KtPs[(h4 * 4 + 2) * 64 + c] = kv[l].z;
            KtPs[(h4 * 4 + 3) * 64 + c] = kv[l].w;
        }

        // issue V loads now; STS deferred until after the S GEMM
        float4 vv[4];
#pragma unroll
        for (int l = 0; l < 4; l++) {
            int idx = tid + l * 256;
            int r = idx >> 4, c4 = idx & 15;
            vv[l] = *(const float4*)&vg[(size_t)(jc0 + r) * HH + c4 * 4];
        }

        __syncthreads();   // K tile visible

        // ---- S = Q K^T ----
        float accS[4][4];
#pragma unroll
        for (int r = 0; r < 4; r++)
#pragma unroll
            for (int c = 0; c < 4; c++) accS[r][c] = 0.f;

#pragma unroll 4
        for (int h = 0; h < 64; h += 4) {
            float4 k0 = *(float4*)&KtPs[(h + 0) * 64 + tx * 4];
            float4 k1 = *(float4*)&KtPs[(h + 1) * 64 + tx * 4];
            float4 k2 = *(float4*)&KtPs[(h + 2) * 64 + tx * 4];
            float4 k3 = *(float4*)&KtPs[(h + 3) * 64 + tx * 4];
#pragma unroll
            for (int r = 0; r < 4; r++) {
                float4 qv = *(float4*)&Qs[(ty * 4 + r) * 64 + h];
                accS[r][0] = fmaf(qv.x, k0.x, accS[r][0]);
                accS[r][1] = fmaf(qv.x, k0.y, accS[r][1]);
                accS[r][2] = fmaf(qv.x, k0.z, accS[r][2]);
                accS[r][3] = fmaf(qv.x, k0.w, accS[r][3]);
                accS[r][0] = fmaf(qv.y, k1.x, accS[r][0]);
                accS[r][1] = fmaf(qv.y, k1.y, accS[r][1]);
                accS[r][2] = fmaf(qv.y, k1.z, accS[r][2]);
                accS[r][3] = fmaf(qv.y, k1.w, accS[r][3]);
                accS[r][0] = fmaf(qv.z, k2.x, accS[r][0]);
                accS[r][1] = fmaf(qv.z, k2.y, accS[r][1]);
                accS[r][2] = fmaf(qv.z, k2.z, accS[r][2]);
                accS[r][3] = fmaf(qv.z, k2.w, accS[r][3]);
                accS[r][0] = fmaf(qv.w, k3.x, accS[r][0]);
                accS[r][1] = fmaf(qv.w, k3.y, accS[r][1]);
                accS[r][2] = fmaf(qv.w, k3.z, accS[r][2]);
                accS[r][3] = fmaf(qv.w, k3.w, accS[r][3]);
            }
        }

        // ---- online softmax ----  scale = 1/sqrt(C) = 1/32
        const bool diag = (j == i);
#pragma unroll
        for (int r = 0; r < 4; r++) {
            const int grow = i * 64 + ty * 4 + r;
            float mloc = -1e30f;
#pragma unroll
            for (int c = 0; c < 4; c++) {
                float s = accS[r][c] * 0.03125f;
                if (diag && (jc0 + tx * 4 + c > grow)) s = -1e30f;
                accS[r][c] = s;
                mloc = fmaxf(mloc, s);
            }
            mloc = fmaxf(mloc, __shfl_xor_sync(0xffffffffu, mloc, 8));
            mloc = fmaxf(mloc, __shfl_xor_sync(0xffffffffu, mloc, 4));
            mloc = fmaxf(mloc, __shfl_xor_sync(0xffffffffu, mloc, 2));
            mloc = fmaxf(mloc, __shfl_xor_sync(0xffffffffu, mloc, 1));
            float mnew  = fmaxf(mrun[r], mloc);
            float alpha = __expf(mrun[r] - mnew);
            mrun[r] = mnew;
            float psum = 0.f;
#pragma unroll
            for (int c = 0; c < 4; c++) {
                float pe = __expf(accS[r][c] - mnew);
                accS[r][c] = pe;            // accS now holds P
                psum += pe;
            }
            psum += __shfl_xor_sync(0xffffffffu, psum, 8);
            psum += __shfl_xor_sync(0xffffffffu, psum, 4);
            psum += __shfl_xor_sync(0xffffffffu, psum, 2);
            psum += __shfl_xor_sync(0xffffffffu, psum, 1);
            lrun[r] = lrun[r] * alpha + psum;
#pragma unroll
            for (int c = 0; c < 4; c++) accO[r][c] *= alpha;
        }

        // V tile store (deferred; LDG latency hidden under S GEMM)
#pragma unroll
        for (int l = 0; l < 4; l++) {
            int idx = tid + l * 256;
            int r = idx >> 4, c4 = idx & 15;
            *(float4*)&Vs[r * 64 + c4 * 4] = vv[l];
        }

        __syncthreads();   // S-phase reads of KtPs done; Vs writes pending sync
        // write P over the K buffer
#pragma unroll
        for (int r = 0; r < 4; r++) {
            float4 pv = make_float4(accS[r][0], accS[r][1], accS[r][2], accS[r][3]);
            *(float4*)&KtPs[(ty * 4 + r) * 64 + tx * 4] = pv;
        }
        __syncthreads();

        // ---- O += P V ----
#pragma unroll 4
        for (int c = 0; c < 64; c += 4) {
            float4 v0 = *(float4*)&Vs[(c + 0) * 64 + tx * 4];
            float4 v1 = *(float4*)&Vs[(c + 1) * 64 + tx * 4];
            float4 v2 = *(float4*)&Vs[(c + 2) * 64 + tx * 4];
            float4 v3 = *(float4*)&Vs[(c + 3) * 64 + tx * 4];
#pragma unroll
            for (int r = 0; r < 4; r++) {
                float4 pv = *(float4*)&KtPs[(ty * 4 + r) * 64 + c];
                accO[r][0] = fmaf(pv.x, v0.x, accO[r][0]);
                accO[r][1] = fmaf(pv.x, v0.y, accO[r][1]);
                accO[r][2] = fmaf(pv.x, v0.z, accO[r][2]);
                accO[r][3] = fmaf(pv.x, v0.w, accO[r][3]);
                accO[r][0] = fmaf(pv.y, v1.x, accO[r][0]);
                accO[r][1] = fmaf(pv.y, v1.y, accO[r][1]);
                accO[r][2] = fmaf(pv.y, v1.z, accO[r][2]);
                accO[r][3] = fmaf(pv.y, v1.w, accO[r][3]);
                accO[r][0] = fmaf(pv.z, v2.x, accO[r][0]);
                accO[r][1] = fmaf(pv.z, v2.y, accO[r][1]);
                accO[r][2] = fmaf(pv.z, v2.z, accO[r][2]);
                accO[r][3] = fmaf(pv.z, v2.w, accO[r][3]);
                accO[r][0] = fmaf(pv.w, v3.x, accO[r][0]);
                accO[r][1] = fmaf(pv.w, v3.y, accO[r][1]);
                accO[r][2] = fmaf(pv.w, v3.z, accO[r][2]);
                accO[r][3] = fmaf(pv.w, v3.w, accO[r][3]);
            }
        }
    }

    // write partial results (unnormalized O + row stats)
    const size_t zu = (size_t)b * NUNITS + z;
#pragma unroll
    for (int r = 0; r < 4; r++) {
        float4 o = make_float4(accO[r][0], accO[r][1], accO[r][2], accO[r][3]);
        *(float4*)&gOp[(zu * 64 + ty * 4 + r) * 64 + tx * 4] = o;
    }
    if (tx == 0) {
#pragma unroll
        for (int r = 0; r < 4; r++) {
            gMp[zu * 64 + ty * 4 + r] = mrun[r];
            gLp[zu * 64 + ty * 4 + r] = lrun[r];
        }
    }
}

// ---------------------------------------------------------------------------
// Kernel 3: combine split-KV partials -> out [B,T,H]
// ---------------------------------------------------------------------------
__global__ __launch_bounds__(256)
void combine(float* __restrict__ out)
{
    const int i  = blockIdx.x;
    const int b  = blockIdx.y;
    const int g  = i >> 2;
    const int nu = g + 1;
    const int zb = 2 * g * (g + 1) + (i & 3) * (g + 1);
    const int tid = threadIdx.x;
    const int r   = tid >> 2;
    const int hb  = (tid & 3) * 16;
    const size_t ub = (size_t)b * NUNITS + zb;

    float mmax = -1e30f;
    for (int u = 0; u < nu; u++)
        mmax = fmaxf(mmax, gMp[(ub + u) * 64 + r]);

    float acc[16];
#pragma unroll
    for (int t = 0; t < 16; t++) acc[t] = 0.f;
    float L = 0.f;

    for (int u = 0; u < nu; u++) {
        const float w = __expf(gMp[(ub + u) * 64 + r] - mmax);
        L += w * gLp[(ub + u) * 64 + r];
        const float4* src = (const float4*)&gOp[((ub + u) * 64 + r) * 64 + hb];
#pragma unroll
        for (int t = 0; t < 4; t++) {
            float4 s = src[t];
            acc[t * 4 + 0] += w * s.x;
            acc[t * 4 + 1] += w * s.y;
            acc[t * 4 + 2] += w * s.z;
            acc[t * 4 + 3] += w * s.w;
        }
    }

    const float inv = 1.f / L;
    float4* dst = (float4*)&out[((size_t)(b * TT + i * 64 + r)) * HH + hb];
#pragma unroll
    for (int t = 0; t < 4; t++)
        dst[t] = make_float4(acc[t * 4 + 0] * inv, acc[t * 4 + 1] * inv,
                             acc[t * 4 + 2] * inv, acc[t * 4 + 3] * inv);
}

// ---------------------------------------------------------------------------
extern "C" void kernel_launch(void* const* d_in, const int* in_sizes, int n_in,
                              void* d_out, int out_size)
{
    (void)in_sizes; (void)n_in; (void)out_size;
    const float* x  = (const float*)d_in[0];
    const float* Wq = (const float*)d_in[1];
    const float* Wk = (const float*)d_in[2];
    const float* Wv = (const float*)d_in[3];
    float* out = (float*)d_out;

    qkv_proj<<<(BB * TT) / 64, 256>>>(x, Wq, Wk, Wv);
    attn_part<<<dim3(NUNITS, BB), 256>>>();
    combine<<<dim3(TT / 64, BB), 256>>>(out);
}

// round 10
// speedup vs baseline: 1.8239x; 1.0638x over previous
#include <cuda_runtime.h>

// Problem constants (fixed by the reference setup_inputs)
#define BB 4
#define TT 4096
#define CCH 1024
#define HH 64

#define CH   8      // KV tiles (of 64) per split-KV unit
#define NU2  144    // units per batch = sum_I ceil((I+1)/4), I in [0,32)

typedef unsigned long long u64;

__device__ __forceinline__ u64 pk2(float v) {
    u64 r; asm("mov.b64 %0, {%1, %1};" : "=l"(r) : "f"(v)); return r;
}
__device__ __forceinline__ u64 f2fma(u64 a, u64 b, u64 c) {
    u64 d; asm("fma.rn.f32x2 %0, %1, %2, %3;" : "=l"(d) : "l"(a), "l"(b), "l"(c)); return d;
}
__device__ __forceinline__ u64 f2mul(u64 a, u64 b) {
    u64 d; asm("mul.rn.f32x2 %0, %1, %2;" : "=l"(d) : "l"(a), "l"(b)); return d;
}
__device__ __forceinline__ float2 up2(u64 v) {
    float lo, hi; asm("mov.b64 {%0, %1}, %2;" : "=f"(lo), "=f"(hi) : "l"(v));
    return make_float2(lo, hi);
}

// Projected q,k,v
__device__ float g_q[BB * TT * HH];
__device__ float g_k[BB * TT * HH];
__device__ float g_v[BB * TT * HH];

// Split-KV partials: per unit a [128 x 64] unnormalized O tile + row stats
__device__ float gOp[(size_t)BB * NU2 * 128 * 64];   // ~18.9 MB
__device__ float gMp[BB * NU2 * 128];
__device__ float gLp[BB * NU2 * 128];

// ---------------------------------------------------------------------------
// Kernel 1: fused QKV projection, f32x2 inner loop.
// [64 x 192] tile per block, K chunks of 32 in smem, 4x12 microtile (6 pairs).
// ---------------------------------------------------------------------------
__global__ __launch_bounds__(256)
void qkv_proj(const float* __restrict__ x, const float* __restrict__ Wq,
              const float* __restrict__ Wk, const float* __restrict__ Wv)
{
    __shared__ __align__(16) float xs[64 * 32];
    __shared__ __align__(16) float ws[32 * 192];

    const int tid  = threadIdx.x;
    const int row0 = blockIdx.x * 64;
    const int ty   = tid >> 4;
    const int tx   = tid & 15;

    u64 acc[4][6];
#pragma unroll
    for (int r = 0; r < 4; r++)
#pragma unroll
        for (int p = 0; p < 6; p++) acc[r][p] = 0ULL;

    for (int kk = 0; kk < CCH; kk += 32) {
        __syncthreads();
#pragma unroll
        for (int l = 0; l < 2; l++) {
            int idx = tid + l * 256;
            int r = idx >> 3, c4 = idx & 7;
            *(float4*)&xs[r * 32 + c4 * 4] =
                *(const float4*)&x[(size_t)(row0 + r) * CCH + kk + c4 * 4];
        }
#pragma unroll
        for (int l = 0; l < 6; l++) {
            int idx = tid + l * 256;
            int kr = idx / 48;
            int c  = (idx % 48) * 4;
            const float* Wsrc = (c < 64) ? Wq : ((c < 128) ? Wk : Wv);
            *(float4*)&ws[kr * 192 + c] =
                *(const float4*)&Wsrc[(size_t)(kk + kr) * HH + (c & 63)];
        }
        __syncthreads();

#pragma unroll 8
        for (int k = 0; k < 32; k++) {
            u64 ap[4];
#pragma unroll
            for (int r = 0; r < 4; r++) ap[r] = pk2(xs[(ty * 4 + r) * 32 + k]);
            const ulonglong2* wrow = (const ulonglong2*)&ws[k * 192 + tx * 12];
            ulonglong2 b01 = wrow[0];
            ulonglong2 b23 = wrow[1];
            ulonglong2 b45 = wrow[2];
#pragma unroll
            for (int r = 0; r < 4; r++) {
                acc[r][0] = f2fma(ap[r], b01.x, acc[r][0]);
                acc[r][1] = f2fma(ap[r], b01.y, acc[r][1]);
                acc[r][2] = f2fma(ap[r], b23.x, acc[r][2]);
                acc[r][3] = f2fma(ap[r], b23.y, acc[r][3]);
                acc[r][4] = f2fma(ap[r], b45.x, acc[r][4]);
                acc[r][5] = f2fma(ap[r], b45.y, acc[r][5]);
            }
        }
    }

#pragma unroll
    for (int r = 0; r < 4; r++) {
        int row = row0 + ty * 4 + r;
#pragma unroll
        for (int p = 0; p < 6; p++) {
            float2 v = up2(acc[r][p]);
            int c0 = tx * 12 + 2 * p;
            float* d0 = (c0 < 64) ? g_q : ((c0 < 128) ? g_k : g_v);
            d0[(size_t)row * HH + (c0 & 63)] = v.x;
            int c1 = c0 + 1;
            float* d1 = (c1 < 64) ? g_q : ((c1 < 128) ? g_k : g_v);
            d1[(size_t)row * HH + (c1 & 63)] = v.y;
        }
    }
}

// ---------------------------------------------------------------------------
// Kernel 2: split-KV causal flash attention, f32x2, Br=128 x Bc=64.
// 128 threads; thread (ty=tid>>3, tx=tid&7) owns rows {ty+16*rr} and cols
// {tx*4..+3, 32+tx*4..+3} -> 8x8 microtile (1 FMA/byte of smem traffic).
// Smem rows padded to 68 floats so Q/P reads (4-row broadcast) and the K
// transpose store are single-phase conflict-free.
// Unit = (batch b, query block I of 128 rows, chunk u of <=8 KV tiles).
// ---------------------------------------------------------------------------
__global__ __launch_bounds__(128, 2)
void attn_part()
{
    extern __shared__ float sm[];
    float* Qs  = sm;                 // [128][68]
    float* KtP = sm + 128 * 68;      // Kt: [64 h][68(c)], then P: [128][68]
    float* Vs  = sm + 2 * 128 * 68;  // [64][64]

    const int tid = threadIdx.x;
    const int ty  = tid >> 3;        // 0..15
    const int tx  = tid & 7;         // 0..7
    const int z   = NU2 - 1 - (int)blockIdx.x;   // heavy units first
    const int b   = blockIdx.y;

    // decode z -> (I, u)
    int I = 0, cum = 0;
    for (;;) {
        int nu = (I + 4) >> 2;       // ceil((I+1)/4)
        if (cum + nu > z) break;
        cum += nu; I++;
    }
    const int u      = z - cum;
    const int ntile  = 2 * I + 2;
    const int j0     = u * CH;
    const int j1     = (j0 + CH < ntile) ? (j0 + CH) : ntile;

    const float* qg = g_q + ((size_t)b * TT + (size_t)I * 128) * HH;
    const float* kg = g_k + (size_t)b * TT * HH;
    const float* vg = g_v + (size_t)b * TT * HH;

    const int c16 = tid & 15;        // transpose-loader column
    const int h4  = tid >> 4;        // 0..7

    // load Q tile [128][64] -> padded smem
#pragma unroll
    for (int l = 0; l < 16; l++) {
        int idx = tid + l * 128;
        int r = idx >> 4, c4 = idx & 15;
        *(float4*)&Qs[r * 68 + c4 * 4] = *(const float4*)&qg[(size_t)r * HH + c4 * 4];
    }

    u64 accO[8][4];
    float mrun[8], lrun[8];
#pragma unroll
    for (int rr = 0; rr < 8; rr++) {
        mrun[rr] = -1e30f;
        lrun[rr] = 0.f;
#pragma unroll
        for (int p = 0; p < 4; p++) accO[rr][p] = 0ULL;
    }

    for (int j = j0; j < j1; j++) {
        const int jc0 = j * 64;

        // prefetch K tile into regs (issued before barrier -> overlaps prev PV)
        float4 kreg[8];
#pragma unroll
        for (int l = 0; l < 8; l++) {
            int row = jc0 + c16 + 16 * (l & 3);
            int hc  = (h4 + 8 * (l >> 2)) * 4;
            kreg[l] = *(const float4*)&kg[(size_t)row * HH + hc];
        }

        __syncthreads();   // prev tile's PV reads of KtP/Vs complete

        // conflict-free transposed store Kt[h][c]
#pragma unroll
        for (int l = 0; l < 8; l++) {
            int c  = c16 + 16 * (l & 3);
            int hb = (h4 + 8 * (l >> 2)) * 4;
            KtP[(hb + 0) * 68 + c] = kreg[l].x;
            KtP[(hb + 1) * 68 + c] = kreg[l].y;
            KtP[(hb + 2) * 68 + c] = kreg[l].z;
            KtP[(hb + 3) * 68 + c] = kreg[l].w;
        }

        __syncthreads();   // Kt visible

        // prefetch V into regs; STS deferred past the S GEMM
        float4 vreg[8];
#pragma unroll
        for (int l = 0; l < 8; l++) {
            int idx = tid + l * 128;
            int r = idx >> 4, c4 = idx & 15;
            vreg[l] = *(const float4*)&vg[(size_t)(jc0 + r) * HH + c4 * 4];
        }

        // ---- S = Q K^T (f32x2, 8x8 microtile) ----
        u64 accS[8][4];
#pragma unroll
        for (int rr = 0; rr < 8; rr++)
#pragma unroll
            for (int p = 0; p < 4; p++) accS[rr][p] = 0ULL;

#pragma unroll 4
        for (int h = 0; h < 64; h += 4) {
            ulonglong2 kA[4], kB[4];
#pragma unroll
            for (int hh = 0; hh < 4; hh++) {
                kA[hh] = *(const ulonglong2*)&KtP[(h + hh) * 68 + tx * 4];
                kB[hh] = *(const ulonglong2*)&KtP[(h + hh) * 68 + 32 + tx * 4];
            }
#pragma unroll
            for (int rr = 0; rr < 8; rr++) {
                float4 qv = *(const float4*)&Qs[(ty + 16 * rr) * 68 + h];
                u64 q0 = pk2(qv.x), q1 = pk2(qv.y), q2 = pk2(qv.z), q3 = pk2(qv.w);
                accS[rr][0] = f2fma(q0, kA[0].x, accS[rr][0]);
                accS[rr][1] = f2fma(q0, kA[0].y, accS[rr][1]);
                accS[rr][2] = f2fma(q0, kB[0].x, accS[rr][2]);
                accS[rr][3] = f2fma(q0, kB[0].y, accS[rr][3]);
                accS[rr][0] = f2fma(q1, kA[1].x, accS[rr][0]);
                accS[rr][1] = f2fma(q1, kA[1].y, accS[rr][1]);
                accS[rr][2] = f2fma(q1, kB[1].x, accS[rr][2]);
                accS[rr][3] = f2fma(q1, kB[1].y, accS[rr][3]);
                accS[rr][0] = f2fma(q2, kA[2].x, accS[rr][0]);
                accS[rr][1] = f2fma(q2, kA[2].y, accS[rr][1]);
                accS[rr][2] = f2fma(q2, kB[2].x, accS[rr][2]);
                accS[rr][3] = f2fma(q2, kB[2].y, accS[rr][3]);
                accS[rr][0] = f2fma(q3, kA[3].x, accS[rr][0]);
                accS[rr][1] = f2fma(q3, kA[3].y, accS[rr][1]);
                accS[rr][2] = f2fma(q3, kB[3].x, accS[rr][2]);
                accS[rr][3] = f2fma(q3, kB[3].y, accS[rr][3]);
            }
        }

        __syncthreads();   // all warps done reading Kt -> safe to write P

        // ---- online softmax (scale 1/sqrt(C) = 1/32) + P write ----
        const bool dom   = (j >= 2 * I);
        const int  coffb = jc0 - I * 128;    // col offset of tile vs row base
#pragma unroll
        for (int rr = 0; rr < 8; rr++) {
            float s[8];
            float2 t;
            t = up2(accS[rr][0]); s[0] = t.x; s[1] = t.y;
            t = up2(accS[rr][1]); s[2] = t.x; s[3] = t.y;
            t = up2(accS[rr][2]); s[4] = t.x; s[5] = t.y;
            t = up2(accS[rr][3]); s[6] = t.x; s[7] = t.y;
            const int rowoff = ty + 16 * rr;
            float mloc = -1e30f;
#pragma unroll
            for (int cc = 0; cc < 8; cc++) {
                float v = s[cc] * 0.03125f;
                int c = (cc < 4) ? (tx * 4 + cc) : (32 + tx * 4 + cc - 4);
                if (dom && (coffb + c > rowoff)) v = -1e30f;
                s[cc] = v;
                mloc = fmaxf(mloc, v);
            }
            mloc = fmaxf(mloc, __shfl_xor_sync(0xffffffffu, mloc, 4));
            mloc = fmaxf(mloc, __shfl_xor_sync(0xffffffffu, mloc, 2));
            mloc = fmaxf(mloc, __shfl_xor_sync(0xffffffffu, mloc, 1));
            float mnew  = fmaxf(mrun[rr], mloc);
            float alpha = __expf(mrun[rr] - mnew);
            mrun[rr] = mnew;
            float psum = 0.f;
#pragma unroll
            for (int cc = 0; cc < 8; cc++) {
                float pe = __expf(s[cc] - mnew);
                s[cc] = pe;
                psum += pe;
            }
            psum += __shfl_xor_sync(0xffffffffu, psum, 4);
            psum += __shfl_xor_sync(0xffffffffu, psum, 2);
            psum += __shfl_xor_sync(0xffffffffu, psum, 1);
            lrun[rr] = lrun[rr] * alpha + psum;
            u64 al = pk2(alpha);
#pragma unroll
            for (int p = 0; p < 4; p++) accO[rr][p] = f2mul(accO[rr][p], al);

            *(float4*)&KtP[rowoff * 68 + tx * 4]      = make_float4(s[0], s[1], s[2], s[3]);
            *(float4*)&KtP[rowoff * 68 + 32 + tx * 4] = make_float4(s[4], s[5], s[6], s[7]);
        }

        // V tile store (LDG latency hidden under S GEMM)
#pragma unroll
        for (int l = 0; l < 8; l++) {
            int idx = tid + l * 128;
            int r = idx >> 4, c4 = idx & 15;
            *(float4*)&Vs[r * 64 + c4 * 4] = vreg[l];
        }

        __syncthreads();   // P and V visible

        // ---- O += P V (f32x2, 8x8 microtile) ----
#pragma unroll 4
        for (int c = 0; c < 64; c += 4) {
            ulonglong2 vA[4], vB[4];
#pragma unroll
            for (int cc = 0; cc < 4; cc++) {
                vA[cc] = *(const ulonglong2*)&Vs[(c + cc) * 64 + tx * 4];
                vB[cc] = *(const ulonglong2*)&Vs[(c + cc) * 64 + 32 + tx * 4];
            }
#pragma unroll
            for (int rr = 0; rr < 8; rr++) {
                float4 pv = *(const float4*)&KtP[(ty + 16 * rr) * 68 + c];
                u64 p0 = pk2(pv.x), p1 = pk2(pv.y), p2 = pk2(pv.z), p3 = pk2(pv.w);
                accO[rr][0] = f2fma(p0, vA[0].x, accO[rr][0]);
                accO[rr][1] = f2fma(p0, vA[0].y, accO[rr][1]);
                accO[rr][2] = f2fma(p0, vB[0].x, accO[rr][2]);
                accO[rr][3] = f2fma(p0, vB[0].y, accO[rr][3]);
                accO[rr][0] = f2fma(p1, vA[1].x, accO[rr][0]);
                accO[rr][1] = f2fma(p1, vA[1].y, accO[rr][1]);
                accO[rr][2] = f2fma(p1, vB[1].x, accO[rr][2]);
                accO[rr][3] = f2fma(p1, vB[1].y, accO[rr][3]);
                accO[rr][0] = f2fma(p2, vA[2].x, accO[rr][0]);
                accO[rr][1] = f2fma(p2, vA[2].y, accO[rr][1]);
                accO[rr][2] = f2fma(p2, vB[2].x, accO[rr][2]);
                accO[rr][3] = f2fma(p2, vB[2].y, accO[rr][3]);
                accO[rr][0] = f2fma(p3, vA[3].x, accO[rr][0]);
                accO[rr][1] = f2fma(p3, vA[3].y, accO[rr][1]);
                accO[rr][2] = f2fma(p3, vB[3].x, accO[rr][2]);
                accO[rr][3] = f2fma(p3, vB[3].y, accO[rr][3]);
            }
        }
    }

    // write partials (unnormalized O + row stats)
    const size_t zu = (size_t)b * NU2 + z;
#pragma unroll
    for (int rr = 0; rr < 8; rr++) {
        const int row = ty + 16 * rr;
        float2 a0 = up2(accO[rr][0]), a1 = up2(accO[rr][1]);
        float2 a2 = up2(accO[rr][2]), a3 = up2(accO[rr][3]);
        *(float4*)&gOp[(zu * 128 + row) * 64 + tx * 4]      = make_float4(a0.x, a0.y, a1.x, a1.y);
        *(float4*)&gOp[(zu * 128 + row) * 64 + 32 + tx * 4] = make_float4(a2.x, a2.y, a3.x, a3.y);
        if (tx == 0) {
            gMp[zu * 128 + row] = mrun[rr];
            gLp[zu * 128 + row] = lrun[rr];
        }
    }
}

// ---------------------------------------------------------------------------
// Kernel 3: combine split-KV partials -> out [B,T,H]
// Block = (query block I, batch b). 256 threads: 2 per row, 32 h each.
// ---------------------------------------------------------------------------
__global__ __launch_bounds__(256)
void combine(float* __restrict__ out)
{
    const int I = blockIdx.x;   // 0..31
    const int b = blockIdx.y;
    int cum = 0;
    for (int m = 0; m < I; m++) cum += (m + 4) >> 2;
    const int nu = (I + 4) >> 2;
    const int r  = threadIdx.x >> 1;
    const int hb = (threadIdx.x & 1) * 32;
    const size_t ub = (size_t)b * NU2 + cum;

    float mmax = -1e30f;
    for (int u = 0; u < nu; u++)
        mmax = fmaxf(mmax, gMp[(ub + u) * 128 + r]);

    float acc[32];
#pragma unroll
    for (int t = 0; t < 32; t++) acc[t] = 0.f;
    float L = 0.f;

    for (int u = 0; u < nu; u++) {
        const float w = __expf(gMp[(ub + u) * 128 + r] - mmax);
        L += w * gLp[(ub + u) * 128 + r];
        const float4* src = (const float4*)&gOp[((ub + u) * 128 + r) * 64 + hb];
#pragma unroll
        for (int t = 0; t < 8; t++) {
            float4 s = src[t];
            acc[t * 4 + 0] += w * s.x;
            acc[t * 4 + 1] += w * s.y;
            acc[t * 4 + 2] += w * s.z;
            acc[t * 4 + 3] += w * s.w;
        }
    }

    const float inv = 1.f / L;
    float4* dst = (float4*)&out[((size_t)(b * TT + I * 128 + r)) * HH + hb];
#pragma unroll
    for (int t = 0; t < 8; t++)
        dst[t] = make_float4(acc[t * 4 + 0] * inv, acc[t * 4 + 1] * inv,
                             acc[t * 4 + 2] * inv, acc[t * 4 + 3] * inv);
}

// ---------------------------------------------------------------------------
extern "C" void kernel_launch(void* const* d_in, const int* in_sizes, int n_in,
                              void* d_out, int out_size)
{
    (void)in_sizes; (void)n_in; (void)out_size;
    const float* x  = (const float*)d_in[0];
    const float* Wq = (const float*)d_in[1];
    const float* Wk = (const float*)d_in[2];
    const float* Wv = (const float*)d_in[3];
    float* out = (float*)d_out;

    const int attn_smem = (2 * 128 * 68 + 64 * 64) * sizeof(float);  // 86016 B
    static int attr_done = 0;
    if (!attr_done) {
        cudaFuncSetAttribute(attn_part, cudaFuncAttributeMaxDynamicSharedMemorySize,
                             attn_smem);
        attr_done = 1;
    }

    qkv_proj<<<(BB * TT) / 64, 256>>>(x, Wq, Wk, Wv);
    attn_part<<<dim3(NU2, BB), 128, attn_smem>>>();
    combine<<<dim3(TT / 128, BB), 256>>>(out);
}

// round 13
// speedup vs baseline: 2.1357x; 1.1709x over previous
#include <cuda_runtime.h>
#include <cuda_bf16.h>
#include <cstdint>

// Problem constants (fixed by the reference setup_inputs)
#define BB 4
#define TT 4096
#define CCH 1024
#define HH 64

#define CH   8      // KV tiles (of 64) per split-KV unit
#define NU2  144    // units per batch = sum_I ceil((I+1)/4), I in [0,32)

typedef unsigned long long u64;

// ---------------- f32x2 helpers (attention path) ----------------
__device__ __forceinline__ u64 pk2(float v) {
    u64 r; asm("mov.b64 %0, {%1, %1};" : "=l"(r) : "f"(v)); return r;
}
__device__ __forceinline__ u64 f2fma(u64 a, u64 b, u64 c) {
    u64 d; asm("fma.rn.f32x2 %0, %1, %2, %3;" : "=l"(d) : "l"(a), "l"(b), "l"(c)); return d;
}
__device__ __forceinline__ u64 f2mul(u64 a, u64 b) {
    u64 d; asm("mul.rn.f32x2 %0, %1, %2;" : "=l"(d) : "l"(a), "l"(b)); return d;
}
__device__ __forceinline__ float2 up2(u64 v) {
    float lo, hi; asm("mov.b64 {%0, %1}, %2;" : "=f"(lo), "=f"(hi) : "l"(v));
    return make_float2(lo, hi);
}

// ---------------- bf16 helpers (qkv mma path) ----------------
__device__ __forceinline__ float bfr(float v) {
    return __bfloat162float(__float2bfloat16(v));
}
// pack (e0 -> low half, e1 -> high half)
__device__ __forceinline__ uint32_t pkbf(float e0, float e1) {
    uint32_t r; asm("cvt.rn.bf16x2.f32 %0, %1, %2;" : "=r"(r) : "f"(e1), "f"(e0)); return r;
}
__device__ __forceinline__ void mma16816(float* c, const uint32_t* a,
                                         uint32_t b0, uint32_t b1) {
    asm volatile(
        "mma.sync.aligned.m16n8k16.row.col.f32.bf16.bf16.f32 "
        "{%0,%1,%2,%3}, {%4,%5,%6,%7}, {%8,%9}, {%0,%1,%2,%3};"
        : "+f"(c[0]), "+f"(c[1]), "+f"(c[2]), "+f"(c[3])
        : "r"(a[0]), "r"(a[1]), "r"(a[2]), "r"(a[3]), "r"(b0), "r"(b1));
}

// Projected q,k,v
__device__ float g_q[BB * TT * HH];
__device__ float g_k[BB * TT * HH];
__device__ float g_v[BB * TT * HH];

// Split-KV partials
__device__ float gOp[(size_t)BB * NU2 * 128 * 64];
__device__ float gMp[BB * NU2 * 128];
__device__ float gLp[BB * NU2 * 128];

// ---------------------------------------------------------------------------
// Kernel 1: QKV projection via mma.sync bf16 (bf16x3 split, fp32 accumulate).
// Block: 256 threads (8 warps) computes [64 rows x 192 cols(q|k|v)].
// Warp w: m-slab = (w&3)*16, n-half = (w>>2)*96 (12 n-tiles of 8).
// K looped in chunks of 64. Smem bf16 tiles, row stride 72 (conflict-free:
// u32 index = 36*row + tc -> bank 4*gid + tc, all 32 distinct per warp).
// ---------------------------------------------------------------------------
#define QSTR 36                     // row stride in u32 (72 bf16)
#define A_HI_OFF 0                  // 64*72*2  = 9216 B
#define A_LO_OFF (64 * QSTR)        // u32 offsets
#define B_HI_OFF (128 * QSTR)
#define B_LO_OFF (128 * QSTR + 192 * QSTR)
#define QK_SMEM_U32 (128 * QSTR + 2 * 192 * QSTR)   // 18432 u32 = 73728 B

__global__ __launch_bounds__(256, 2)
void qkv_mma(const float* __restrict__ x, const float* __restrict__ Wq,
             const float* __restrict__ Wk, const float* __restrict__ Wv)
{
    extern __shared__ uint32_t smu[];
    uint32_t* A_hi = smu + A_HI_OFF;
    uint32_t* A_lo = smu + A_LO_OFF;
    uint32_t* B_hi = smu + B_HI_OFF;
    uint32_t* B_lo = smu + B_LO_OFF;

    const int tid  = threadIdx.x;
    const int warp = tid >> 5;
    const int lane = tid & 31;
    const int gid  = lane >> 2;     // 0..7
    const int tc   = lane & 3;      // 0..3
    const int m0   = (warp & 3) * 16;
    const int nh   = (warp >> 2) * 96;
    const int row0 = blockIdx.x * 64;

    float acc[12][4];
#pragma unroll
    for (int nt = 0; nt < 12; nt++)
#pragma unroll
        for (int q = 0; q < 4; q++) acc[nt][q] = 0.f;

    for (int kk = 0; kk < CCH; kk += 64) {
        __syncthreads();   // previous chunk's frag reads complete

        // ---- convert x[64][64] -> A_hi/A_lo (thread: 8 (m,k2) pairs) ----
#pragma unroll
        for (int l = 0; l < 8; l++) {
            int idx = tid + l * 256;          // 0..2047
            int m = idx >> 5, k2 = idx & 31;
            float2 v = *(const float2*)&x[(size_t)(row0 + m) * CCH + kk + 2 * k2];
            A_hi[m * QSTR + k2] = pkbf(v.x, v.y);
            A_lo[m * QSTR + k2] = pkbf(v.x - bfr(v.x), v.y - bfr(v.y));
        }
        // ---- convert W (transposed) -> B_hi/B_lo (thread: 24 (k2,n) pairs) ----
#pragma unroll
        for (int l = 0; l < 24; l++) {
            int idx = tid + l * 256;          // 0..6143
            int k2 = idx / 192, n = idx % 192;
            const float* Wsrc = (n < 64) ? Wq : ((n < 128) ? Wk : Wv);
            const int h = n & 63;
            float w0 = Wsrc[(size_t)(kk + 2 * k2) * HH + h];
            float w1 = Wsrc[(size_t)(kk + 2 * k2 + 1) * HH + h];
            B_hi[n * QSTR + k2] = pkbf(w0, w1);
            B_lo[n * QSTR + k2] = pkbf(w0 - bfr(w0), w1 - bfr(w1));
        }
        __syncthreads();

        // ---- 4 k16 steps ----
#pragma unroll
        for (int kt = 0; kt < 4; kt++) {
            const int kb = kt * 8;
            uint32_t aH[4], aL[4];
            {
                const int ra = (m0 + gid) * QSTR + kb + tc;
                aH[0] = A_hi[ra];
                aH[1] = A_hi[ra + 8 * QSTR];
                aH[2] = A_hi[ra + 4];
                aH[3] = A_hi[ra + 8 * QSTR + 4];
                aL[0] = A_lo[ra];
                aL[1] = A_lo[ra + 8 * QSTR];
                aL[2] = A_lo[ra + 4];
                aL[3] = A_lo[ra + 8 * QSTR + 4];
            }
#pragma unroll
            for (int nt = 0; nt < 12; nt++) {
                const int rb = (nh + nt * 8 + gid) * QSTR + kb + tc;
                uint32_t bH0 = B_hi[rb], bH1 = B_hi[rb + 4];
                uint32_t bL0 = B_lo[rb], bL1 = B_lo[rb + 4];
                mma16816(acc[nt], aH, bH0, bH1);
                mma16816(acc[nt], aH, bL0, bL1);
                mma16816(acc[nt], aL, bH0, bH1);
            }
        }
    }

    // ---- epilogue: C frag (c0,c1)->row gid, (c2,c3)->row gid+8, cols tc*2 ----
    const int rowA = row0 + m0 + gid;
#pragma unroll
    for (int nt = 0; nt < 12; nt++) {
        const int col = nh + nt * 8 + tc * 2;
        float* dst = (col < 64) ? g_q : ((col < 128) ? g_k : g_v);
        const int c = col & 63;
        *(float2*)&dst[(size_t)rowA * HH + c]       = make_float2(acc[nt][0], acc[nt][1]);
        *(float2*)&dst[(size_t)(rowA + 8) * HH + c] = make_float2(acc[nt][2], acc[nt][3]);
    }
}

// ---------------------------------------------------------------------------
// Kernel 2: split-KV causal flash attention, f32x2, Br=128 x Bc=64 (round 9).
// ---------------------------------------------------------------------------
__global__ __launch_bounds__(128, 2)
void attn_part()
{
    extern __shared__ float sm[];
    float* Qs  = sm;                 // [128][68]
    float* KtP = sm + 128 * 68;      // Kt: [64 h][68(c)], then P: [128][68]
    float* Vs  = sm + 2 * 128 * 68;  // [64][64]

    const int tid = threadIdx.x;
    const int ty  = tid >> 3;
    const int tx  = tid & 7;
    const int z   = NU2 - 1 - (int)blockIdx.x;
    const int b   = blockIdx.y;

    int I = 0, cum = 0;
    for (;;) {
        int nu = (I + 4) >> 2;
        if (cum + nu > z) break;
        cum += nu; I++;
    }
    const int u     = z - cum;
    const int ntile = 2 * I + 2;
    const int j0    = u * CH;
    const int j1    = (j0 + CH < ntile) ? (j0 + CH) : ntile;

    const float* qg = g_q + ((size_t)b * TT + (size_t)I * 128) * HH;
    const float* kg = g_k + (size_t)b * TT * HH;
    const float* vg = g_v + (size_t)b * TT * HH;

    const int c16 = tid & 15;
    const int h4  = tid >> 4;

#pragma unroll
    for (int l = 0; l < 16; l++) {
        int idx = tid + l * 128;
        int r = idx >> 4, c4 = idx & 15;
        *(float4*)&Qs[r * 68 + c4 * 4] = *(const float4*)&qg[(size_t)r * HH + c4 * 4];
    }

    u64 accO[8][4];
    float mrun[8], lrun[8];
#pragma unroll
    for (int rr = 0; rr < 8; rr++) {
        mrun[rr] = -1e30f;
        lrun[rr] = 0.f;
#pragma unroll
        for (int p = 0; p < 4; p++) accO[rr][p] = 0ULL;
    }

    for (int j = j0; j < j1; j++) {
        const int jc0 = j * 64;

        float4 kreg[8];
#pragma unroll
        for (int l = 0; l < 8; l++) {
            int row = jc0 + c16 + 16 * (l & 3);
            int hc  = (h4 + 8 * (l >> 2)) * 4;
            kreg[l] = *(const float4*)&kg[(size_t)row * HH + hc];
        }

        __syncthreads();

#pragma unroll
        for (int l = 0; l < 8; l++) {
            int c  = c16 + 16 * (l & 3);
            int hb = (h4 + 8 * (l >> 2)) * 4;
            KtP[(hb + 0) * 68 + c] = kreg[l].x;
            KtP[(hb + 1) * 68 + c] = kreg[l].y;
            KtP[(hb + 2) * 68 + c] = kreg[l].z;
            KtP[(hb + 3) * 68 + c] = kreg[l].w;
        }

        __syncthreads();

        float4 vreg[8];
#pragma unroll
        for (int l = 0; l < 8; l++) {
            int idx = tid + l * 128;
            int r = idx >> 4, c4 = idx & 15;
            vreg[l] = *(const float4*)&vg[(size_t)(jc0 + r) * HH + c4 * 4];
        }

        u64 accS[8][4];
#pragma unroll
        for (int rr = 0; rr < 8; rr++)
#pragma unroll
            for (int p = 0; p < 4; p++) accS[rr][p] = 0ULL;

#pragma unroll 4
        for (int h = 0; h < 64; h += 4) {
            ulonglong2 kA[4], kB[4];
#pragma unroll
            for (int hh = 0; hh < 4; hh++) {
                kA[hh] = *(const ulonglong2*)&KtP[(h + hh) * 68 + tx * 4];
                kB[hh] = *(const ulonglong2*)&KtP[(h + hh) * 68 + 32 + tx * 4];
            }
#pragma unroll
            for (int rr = 0; rr < 8; rr++) {
                float4 qv = *(const float4*)&Qs[(ty + 16 * rr) * 68 + h];
                u64 q0 = pk2(qv.x), q1 = pk2(qv.y), q2 = pk2(qv.z), q3 = pk2(qv.w);
                accS[rr][0] = f2fma(q0, kA[0].x, accS[rr][0]);
                accS[rr][1] = f2fma(q0, kA[0].y, accS[rr][1]);
                accS[rr][2] = f2fma(q0, kB[0].x, accS[rr][2]);
                accS[rr][3] = f2fma(q0, kB[0].y, accS[rr][3]);
                accS[rr][0] = f2fma(q1, kA[1].x, accS[rr][0]);
                accS[rr][1] = f2fma(q1, kA[1].y, accS[rr][1]);
                accS[rr][2] = f2fma(q1, kB[1].x, accS[rr][2]);
                accS[rr][3] = f2fma(q1, kB[1].y, accS[rr][3]);
                accS[rr][0] = f2fma(q2, kA[2].x, accS[rr][0]);
                accS[rr][1] = f2fma(q2, kA[2].y, accS[rr][1]);
                accS[rr][2] = f2fma(q2, kB[2].x, accS[rr][2]);
                accS[rr][3] = f2fma(q2, kB[2].y, accS[rr][3]);
                accS[rr][0] = f2fma(q3, kA[3].x, accS[rr][0]);
                accS[rr][1] = f2fma(q3, kA[3].y, accS[rr][1]);
                accS[rr][2] = f2fma(q3, kB[3].x, accS[rr][2]);
                accS[rr][3] = f2fma(q3, kB[3].y, accS[rr][3]);
            }
        }

        __syncthreads();

        const bool dom   = (j >= 2 * I);
        const int  coffb = jc0 - I * 128;
#pragma unroll
        for (int rr = 0; rr < 8; rr++) {
            float s[8];
            float2 t;
            t = up2(accS[rr][0]); s[0] = t.x; s[1] = t.y;
            t = up2(accS[rr][1]); s[2] = t.x; s[3] = t.y;
            t = up2(accS[rr][2]); s[4] = t.x; s[5] = t.y;
            t = up2(accS[rr][3]); s[6] = t.x; s[7] = t.y;
            const int rowoff = ty + 16 * rr;
            float mloc = -1e30f;
#pragma unroll
            for (int cc = 0; cc < 8; cc++) {
                float v = s[cc] * 0.03125f;
                int c = (cc < 4) ? (tx * 4 + cc) : (32 + tx * 4 + cc - 4);
                if (dom && (coffb + c > rowoff)) v = -1e30f;
                s[cc] = v;
                mloc = fmaxf(mloc, v);
            }
            mloc = fmaxf(mloc, __shfl_xor_sync(0xffffffffu, mloc, 4));
            mloc = fmaxf(mloc, __shfl_xor_sync(0xffffffffu, mloc, 2));
            mloc = fmaxf(mloc, __shfl_xor_sync(0xffffffffu, mloc, 1));
            float mnew  = fmaxf(mrun[rr], mloc);
            float alpha = __expf(mrun[rr] - mnew);
            mrun[rr] = mnew;
            float psum = 0.f;
#pragma unroll
            for (int cc = 0; cc < 8; cc++) {
                float pe = __expf(s[cc] - mnew);
                s[cc] = pe;
                psum += pe;
            }
            psum += __shfl_xor_sync(0xffffffffu, psum, 4);
            psum += __shfl_xor_sync(0xffffffffu, psum, 2);
            psum += __shfl_xor_sync(0xffffffffu, psum, 1);
            lrun[rr] = lrun[rr] * alpha + psum;
            u64 al = pk2(alpha);
#pragma unroll
            for (int p = 0; p < 4; p++) accO[rr][p] = f2mul(accO[rr][p], al);

            *(float4*)&KtP[rowoff * 68 + tx * 4]      = make_float4(s[0], s[1], s[2], s[3]);
            *(float4*)&KtP[rowoff * 68 + 32 + tx * 4] = make_float4(s[4], s[5], s[6], s[7]);
        }

#pragma unroll
        for (int l = 0; l < 8; l++) {
            int idx = tid + l * 128;
            int r = idx >> 4, c4 = idx & 15;
            *(float4*)&Vs[r * 64 + c4 * 4] = vreg[l];
        }

        __syncthreads();

#pragma unroll 4
        for (int c = 0; c < 64; c += 4) {
            ulonglong2 vA[4], vB[4];
#pragma unroll
            for (int cc = 0; cc < 4; cc++) {
                vA[cc] = *(const ulonglong2*)&Vs[(c + cc) * 64 + tx * 4];
                vB[cc] = *(const ulonglong2*)&Vs[(c + cc) * 64 + 32 + tx * 4];
            }
#pragma unroll
            for (int rr = 0; rr < 8; rr++) {
                float4 pv = *(const float4*)&KtP[(ty + 16 * rr) * 68 + c];
                u64 p0 = pk2(pv.x), p1 = pk2(pv.y), p2 = pk2(pv.z), p3 = pk2(pv.w);
                accO[rr][0] = f2fma(p0, vA[0].x, accO[rr][0]);
                accO[rr][1] = f2fma(p0, vA[0].y, accO[rr][1]);
                accO[rr][2] = f2fma(p0, vB[0].x, accO[rr][2]);
                accO[rr][3] = f2fma(p0, vB[0].y, accO[rr][3]);
                accO[rr][0] = f2fma(p1, vA[1].x, accO[rr][0]);
                accO[rr][1] = f2fma(p1, vA[1].y, accO[rr][1]);
                accO[rr][2] = f2fma(p1, vB[1].x, accO[rr][2]);
                accO[rr][3] = f2fma(p1, vB[1].y, accO[rr][3]);
                accO[rr][0] = f2fma(p2, vA[2].x, accO[rr][0]);
                accO[rr][1] = f2fma(p2, vA[2].y, accO[rr][1]);
                accO[rr][2] = f2fma(p2, vB[2].x, accO[rr][2]);
                accO[rr][3] = f2fma(p2, vB[2].y, accO[rr][3]);
                accO[rr][0] = f2fma(p3, vA[3].x, accO[rr][0]);
                accO[rr][1] = f2fma(p3, vA[3].y, accO[rr][1]);
                accO[rr][2] = f2fma(p3, vB[3].x, accO[rr][2]);
                accO[rr][3] = f2fma(p3, vB[3].y, accO[rr][3]);
            }
        }
    }

    const size_t zu = (size_t)b * NU2 + z;
#pragma unroll
    for (int rr = 0; rr < 8; rr++) {
        const int row = ty + 16 * rr;
        float2 a0 = up2(accO[rr][0]), a1 = up2(accO[rr][1]);
        float2 a2 = up2(accO[rr][2]), a3 = up2(accO[rr][3]);
        *(float4*)&gOp[(zu * 128 + row) * 64 + tx * 4]      = make_float4(a0.x, a0.y, a1.x, a1.y);
        *(float4*)&gOp[(zu * 128 + row) * 64 + 32 + tx * 4] = make_float4(a2.x, a2.y, a3.x, a3.y);
        if (tx == 0) {
            gMp[zu * 128 + row] = mrun[rr];
            gLp[zu * 128 + row] = lrun[rr];
        }
    }
}

// ---------------------------------------------------------------------------
// Kernel 3: combine split-KV partials -> out [B,T,H]
// ---------------------------------------------------------------------------
__global__ __launch_bounds__(256)
void combine(float* __restrict__ out)
{
    const int I = blockIdx.x;
    const int b = blockIdx.y;
    int cum = 0;
    for (int m = 0; m < I; m++) cum += (m + 4) >> 2;
    const int nu = (I + 4) >> 2;
    const int r  = threadIdx.x >> 1;
    const int hb = (threadIdx.x & 1) * 32;
    const size_t ub = (size_t)b * NU2 + cum;

    float mmax = -1e30f;
    for (int u = 0; u < nu; u++)
        mmax = fmaxf(mmax, gMp[(ub + u) * 128 + r]);

    float acc[32];
#pragma unroll
    for (int t = 0; t < 32; t++) acc[t] = 0.f;
    float L = 0.f;

    for (int u = 0; u < nu; u++) {
        const float w = __expf(gMp[(ub + u) * 128 + r] - mmax);
        L += w * gLp[(ub + u) * 128 + r];
        const float4* src = (const float4*)&gOp[((ub + u) * 128 + r) * 64 + hb];
#pragma unroll
        for (int t = 0; t < 8; t++) {
            float4 s = src[t];
            acc[t * 4 + 0] += w * s.x;
            acc[t * 4 + 1] += w * s.y;
            acc[t * 4 + 2] += w * s.z;
            acc[t * 4 + 3] += w * s.w;
        }
    }

    const float inv = 1.f / L;
    float4* dst = (float4*)&out[((size_t)(b * TT + I * 128 + r)) * HH + hb];
#pragma unroll
    for (int t = 0; t < 8; t++)
        dst[t] = make_float4(acc[t * 4 + 0] * inv, acc[t * 4 + 1] * inv,
                             acc[t * 4 + 2] * inv, acc[t * 4 + 3] * inv);
}

// ---------------------------------------------------------------------------
extern "C" void kernel_launch(void* const* d_in, const int* in_sizes, int n_in,
                              void* d_out, int out_size)
{
    (void)in_sizes; (void)n_in; (void)out_size;
    const float* x  = (const float*)d_in[0];
    const float* Wq = (const float*)d_in[1];
    const float* Wk = (const float*)d_in[2];
    const float* Wv = (const float*)d_in[3];
    float* out = (float*)d_out;

    const int attn_smem = (2 * 128 * 68 + 64 * 64) * sizeof(float);  // 86016 B
    const int qkv_smem  = QK_SMEM_U32 * 4;                           // 73728 B
    static int attr_done = 0;
    if (!attr_done) {
        cudaFuncSetAttribute(attn_part, cudaFuncAttributeMaxDynamicSharedMemorySize,
                             attn_smem);
        cudaFuncSetAttribute(qkv_mma, cudaFuncAttributeMaxDynamicSharedMemorySize,
                             qkv_smem);
        attr_done = 1;
    }

    qkv_mma<<<(BB * TT) / 64, 256, qkv_smem>>>(x, Wq, Wk, Wv);
    attn_part<<<dim3(NU2, BB), 128, attn_smem>>>();
    combine<<<dim3(TT / 128, BB), 256>>>(out);
}

// round 14
// speedup vs baseline: 3.0447x; 1.4256x over previous
#include <cuda_runtime.h>
#include <cuda_bf16.h>
#include <cstdint>

// Problem constants (fixed by the reference setup_inputs)
#define BB 4
#define TT 4096
#define CCH 1024
#define HH 64

#define CH   8      // KV tiles (of 64) per split-KV unit
#define NU2  144    // units per batch = sum_I ceil((I+1)/4), I in [0,32)

// ---------------- bf16 / mma helpers ----------------
__device__ __forceinline__ float bfr(float v) {
    return __bfloat162float(__float2bfloat16(v));
}
// pack (e0 -> low half, e1 -> high half)
__device__ __forceinline__ uint32_t pkbf(float e0, float e1) {
    uint32_t r; asm("cvt.rn.bf16x2.f32 %0, %1, %2;" : "=r"(r) : "f"(e1), "f"(e0)); return r;
}
__device__ __forceinline__ void mma16816(float* c, const uint32_t* a,
                                         uint32_t b0, uint32_t b1) {
    asm volatile(
        "mma.sync.aligned.m16n8k16.row.col.f32.bf16.bf16.f32 "
        "{%0,%1,%2,%3}, {%4,%5,%6,%7}, {%8,%9}, {%0,%1,%2,%3};"
        : "+f"(c[0]), "+f"(c[1]), "+f"(c[2]), "+f"(c[3])
        : "r"(a[0]), "r"(a[1]), "r"(a[2]), "r"(a[3]), "r"(b0), "r"(b1));
}

// Projected q,k,v
__device__ float g_q[BB * TT * HH];
__device__ float g_k[BB * TT * HH];
__device__ float g_v[BB * TT * HH];

// Split-KV partials
__device__ float gOp[(size_t)BB * NU2 * 128 * 64];
__device__ float gMp[BB * NU2 * 128];
__device__ float gLp[BB * NU2 * 128];

// ---------------------------------------------------------------------------
// Kernel 1: QKV projection via mma.sync bf16 (bf16x3 split). Round-12 version.
// ---------------------------------------------------------------------------
#define QSTR 36                     // row stride in u32 (72 bf16)
#define A_HI_OFF 0
#define A_LO_OFF (64 * QSTR)
#define B_HI_OFF (128 * QSTR)
#define B_LO_OFF (128 * QSTR + 192 * QSTR)
#define QK_SMEM_U32 (128 * QSTR + 2 * 192 * QSTR)   // 18432 u32 = 73728 B

__global__ __launch_bounds__(256, 2)
void qkv_mma(const float* __restrict__ x, const float* __restrict__ Wq,
             const float* __restrict__ Wk, const float* __restrict__ Wv)
{
    extern __shared__ uint32_t smu[];
    uint32_t* A_hi = smu + A_HI_OFF;
    uint32_t* A_lo = smu + A_LO_OFF;
    uint32_t* B_hi = smu + B_HI_OFF;
    uint32_t* B_lo = smu + B_LO_OFF;

    const int tid  = threadIdx.x;
    const int warp = tid >> 5;
    const int lane = tid & 31;
    const int gid  = lane >> 2;
    const int tc   = lane & 3;
    const int m0   = (warp & 3) * 16;
    const int nh   = (warp >> 2) * 96;
    const int row0 = blockIdx.x * 64;

    float acc[12][4];
#pragma unroll
    for (int nt = 0; nt < 12; nt++)
#pragma unroll
        for (int q = 0; q < 4; q++) acc[nt][q] = 0.f;

    for (int kk = 0; kk < CCH; kk += 64) {
        __syncthreads();

#pragma unroll
        for (int l = 0; l < 8; l++) {
            int idx = tid + l * 256;
            int m = idx >> 5, k2 = idx & 31;
            float2 v = *(const float2*)&x[(size_t)(row0 + m) * CCH + kk + 2 * k2];
            A_hi[m * QSTR + k2] = pkbf(v.x, v.y);
            A_lo[m * QSTR + k2] = pkbf(v.x - bfr(v.x), v.y - bfr(v.y));
        }
#pragma unroll
        for (int l = 0; l < 24; l++) {
            int idx = tid + l * 256;
            int k2 = idx / 192, n = idx % 192;
            const float* Wsrc = (n < 64) ? Wq : ((n < 128) ? Wk : Wv);
            const int h = n & 63;
            float w0 = Wsrc[(size_t)(kk + 2 * k2) * HH + h];
            float w1 = Wsrc[(size_t)(kk + 2 * k2 + 1) * HH + h];
            B_hi[n * QSTR + k2] = pkbf(w0, w1);
            B_lo[n * QSTR + k2] = pkbf(w0 - bfr(w0), w1 - bfr(w1));
        }
        __syncthreads();

#pragma unroll
        for (int kt = 0; kt < 4; kt++) {
            const int kb = kt * 8;
            uint32_t aH[4], aL[4];
            {
                const int ra = (m0 + gid) * QSTR + kb + tc;
                aH[0] = A_hi[ra];
                aH[1] = A_hi[ra + 8 * QSTR];
                aH[2] = A_hi[ra + 4];
                aH[3] = A_hi[ra + 8 * QSTR + 4];
                aL[0] = A_lo[ra];
                aL[1] = A_lo[ra + 8 * QSTR];
                aL[2] = A_lo[ra + 4];
                aL[3] = A_lo[ra + 8 * QSTR + 4];
            }
#pragma unroll
            for (int nt = 0; nt < 12; nt++) {
                const int rb = (nh + nt * 8 + gid) * QSTR + kb + tc;
                uint32_t bH0 = B_hi[rb], bH1 = B_hi[rb + 4];
                uint32_t bL0 = B_lo[rb], bL1 = B_lo[rb + 4];
                mma16816(acc[nt], aH, bH0, bH1);
                mma16816(acc[nt], aH, bL0, bL1);
                mma16816(acc[nt], aL, bH0, bH1);
            }
        }
    }

    const int rowA = row0 + m0 + gid;
#pragma unroll
    for (int nt = 0; nt < 12; nt++) {
        const int col = nh + nt * 8 + tc * 2;
        float* dst = (col < 64) ? g_q : ((col < 128) ? g_k : g_v);
        const int c = col & 63;
        *(float2*)&dst[(size_t)rowA * HH + c]       = make_float2(acc[nt][0], acc[nt][1]);
        *(float2*)&dst[(size_t)(rowA + 8) * HH + c] = make_float2(acc[nt][2], acc[nt][3]);
    }
}

// ---------------------------------------------------------------------------
// Kernel 2: split-KV causal flash attention via mma.sync bf16 (bf16x3 split).
// 256 threads (8 warps), Br=128 x Bc=64. Warp w owns the 16-row slab w*16.
// Smem u32 tiles, row stride 36 (all fragment LDS conflict-free).
//   Qh/Ql [128][36], Kh/Kl [64 keys][36] ([key][head] = B-frag layout for S),
//   Vh/Vl [64 heads][36] (V transposed: [head][key] = B-frag layout for PV).
// P stays in registers: S-accumulator C-frag layout == PV A-frag layout.
// ---------------------------------------------------------------------------
#define AQ_H 0
#define AQ_L (128 * QSTR)
#define AK_H (2 * 128 * QSTR)
#define AK_L (2 * 128 * QSTR + 64 * QSTR)
#define AV_H (2 * 128 * QSTR + 2 * 64 * QSTR)
#define AV_L (2 * 128 * QSTR + 3 * 64 * QSTR)
#define AT_SMEM_U32 (2 * 128 * QSTR + 4 * 64 * QSTR)   // 18432 u32 = 73728 B

__global__ __launch_bounds__(256)
void attn_mma()
{
    extern __shared__ uint32_t su[];
    uint32_t* Qh = su + AQ_H;
    uint32_t* Ql = su + AQ_L;
    uint32_t* Kh = su + AK_H;
    uint32_t* Kl = su + AK_L;
    uint32_t* Vh = su + AV_H;
    uint32_t* Vl = su + AV_L;

    const int tid  = threadIdx.x;
    const int warp = tid >> 5;
    const int lane = tid & 31;
    const int gid  = lane >> 2;
    const int tc   = lane & 3;
    const int z    = NU2 - 1 - (int)blockIdx.x;   // heavy units first
    const int b    = blockIdx.y;

    // decode z -> (I, u)
    int I = 0, cum = 0;
    for (;;) {
        int nu = (I + 4) >> 2;
        if (cum + nu > z) break;
        cum += nu; I++;
    }
    const int u     = z - cum;
    const int ntile = 2 * I + 2;
    const int j0    = u * CH;
    const int j1    = (j0 + CH < ntile) ? (j0 + CH) : ntile;

    const float* qg = g_q + ((size_t)b * TT + (size_t)I * 128) * HH;
    const float* kg = g_k + (size_t)b * TT * HH;
    const float* vg = g_v + (size_t)b * TT * HH;

    // ---- convert Q tile [128][64] -> Qh/Ql ----
#pragma unroll
    for (int l = 0; l < 16; l++) {
        int idx = tid + l * 256;            // over 128*32 u32 slots
        int m = idx >> 5, k2 = idx & 31;
        float2 v = *(const float2*)&qg[(size_t)m * HH + 2 * k2];
        Qh[m * QSTR + k2] = pkbf(v.x, v.y);
        Ql[m * QSTR + k2] = pkbf(v.x - bfr(v.x), v.y - bfr(v.y));
    }

    float accO[8][4];
    float mrun[2], lrun[2];
#pragma unroll
    for (int nt = 0; nt < 8; nt++)
#pragma unroll
        for (int q = 0; q < 4; q++) accO[nt][q] = 0.f;
    mrun[0] = mrun[1] = -1e30f;
    lrun[0] = lrun[1] = 0.f;

    const int rslab = warp * 16 + gid;      // row r0 within the 128-row block

    for (int j = j0; j < j1; j++) {
        const int jc0 = j * 64;

        // prefetch K [64][64] and V (transposed access) into regs
        float2 kreg[8];
#pragma unroll
        for (int l = 0; l < 8; l++) {
            int idx = tid + l * 256;
            int m = idx >> 5, k2 = idx & 31;
            kreg[l] = *(const float2*)&kg[(size_t)(jc0 + m) * HH + 2 * k2];
        }
        float2 vreg[8];
#pragma unroll
        for (int l = 0; l < 8; l++) {
            int idx = tid + l * 256;
            int key2 = idx >> 6, head = idx & 63;
            vreg[l].x = vg[(size_t)(jc0 + 2 * key2) * HH + head];
            vreg[l].y = vg[(size_t)(jc0 + 2 * key2 + 1) * HH + head];
        }

        __syncthreads();   // previous tile's fragment reads complete (also Q, 1st iter)

#pragma unroll
        for (int l = 0; l < 8; l++) {
            int idx = tid + l * 256;
            int m = idx >> 5, k2 = idx & 31;
            Kh[m * QSTR + k2] = pkbf(kreg[l].x, kreg[l].y);
            Kl[m * QSTR + k2] = pkbf(kreg[l].x - bfr(kreg[l].x),
                                     kreg[l].y - bfr(kreg[l].y));
        }
#pragma unroll
        for (int l = 0; l < 8; l++) {
            int idx = tid + l * 256;
            int key2 = idx >> 6, head = idx & 63;
            Vh[head * QSTR + key2] = pkbf(vreg[l].x, vreg[l].y);
            Vl[head * QSTR + key2] = pkbf(vreg[l].x - bfr(vreg[l].x),
                                          vreg[l].y - bfr(vreg[l].y));
        }
        __syncthreads();

        // ---- S = Q K^T (bf16x3) ----
        float accS[8][4];
#pragma unroll
        for (int nt = 0; nt < 8; nt++)
#pragma unroll
            for (int q = 0; q < 4; q++) accS[nt][q] = 0.f;

#pragma unroll
        for (int kt = 0; kt < 4; kt++) {
            const int kb = kt * 8;
            uint32_t aH[4], aL[4];
            {
                const int ra = rslab * QSTR + kb + tc;
                aH[0] = Qh[ra];
                aH[1] = Qh[ra + 8 * QSTR];
                aH[2] = Qh[ra + 4];
                aH[3] = Qh[ra + 8 * QSTR + 4];
                aL[0] = Ql[ra];
                aL[1] = Ql[ra + 8 * QSTR];
                aL[2] = Ql[ra + 4];
                aL[3] = Ql[ra + 8 * QSTR + 4];
            }
#pragma unroll
            for (int nt = 0; nt < 8; nt++) {
                const int rb = (nt * 8 + gid) * QSTR + kb + tc;
                uint32_t bH0 = Kh[rb], bH1 = Kh[rb + 4];
                uint32_t bL0 = Kl[rb], bL1 = Kl[rb + 4];
                mma16816(accS[nt], aH, bH0, bH1);
                mma16816(accS[nt], aH, bL0, bL1);
                mma16816(accS[nt], aL, bH0, bH1);
            }
        }

        // ---- online softmax (scale 1/sqrt(C) = 1/32); accS -> P ----
        const bool dom   = (j >= 2 * I);
        const int  coffb = jc0 - I * 128;
#pragma unroll
        for (int h = 0; h < 2; h++) {
            const int rowoff = rslab + h * 8;
            float sv[16];
            float mloc = -1e30f;
#pragma unroll
            for (int nt = 0; nt < 8; nt++) {
                float v0 = accS[nt][2 * h]     * 0.03125f;
                float v1 = accS[nt][2 * h + 1] * 0.03125f;
                const int c0 = nt * 8 + tc * 2;
                if (dom) {
                    if (coffb + c0 > rowoff)     v0 = -1e30f;
                    if (coffb + c0 + 1 > rowoff) v1 = -1e30f;
                }
                sv[2 * nt] = v0; sv[2 * nt + 1] = v1;
                mloc = fmaxf(mloc, fmaxf(v0, v1));
            }
            mloc = fmaxf(mloc, __shfl_xor_sync(0xffffffffu, mloc, 1));
            mloc = fmaxf(mloc, __shfl_xor_sync(0xffffffffu, mloc, 2));
            float mnew  = fmaxf(mrun[h], mloc);
            float alpha = __expf(mrun[h] - mnew);
            mrun[h] = mnew;
            float psum = 0.f;
#pragma unroll
            for (int t = 0; t < 16; t++) {
                float pe = __expf(sv[t] - mnew);
                sv[t] = pe;
                psum += pe;
            }
            psum += __shfl_xor_sync(0xffffffffu, psum, 1);
            psum += __shfl_xor_sync(0xffffffffu, psum, 2);
            lrun[h] = lrun[h] * alpha + psum;
#pragma unroll
            for (int nt = 0; nt < 8; nt++) {
                accS[nt][2 * h]     = sv[2 * nt];
                accS[nt][2 * h + 1] = sv[2 * nt + 1];
                accO[nt][2 * h]     *= alpha;
                accO[nt][2 * h + 1] *= alpha;
            }
        }

        // ---- O += P V (bf16x3; P packed from registers) ----
#pragma unroll
        for (int kt = 0; kt < 4; kt++) {
            const int kb = kt * 8;
            uint32_t aPh[4], aPl[4];
            {
                const float p00 = accS[2 * kt][0],     p01 = accS[2 * kt][1];
                const float p10 = accS[2 * kt][2],     p11 = accS[2 * kt][3];
                const float q00 = accS[2 * kt + 1][0], q01 = accS[2 * kt + 1][1];
                const float q10 = accS[2 * kt + 1][2], q11 = accS[2 * kt + 1][3];
                aPh[0] = pkbf(p00, p01);
                aPh[1] = pkbf(p10, p11);
                aPh[2] = pkbf(q00, q01);
                aPh[3] = pkbf(q10, q11);
                aPl[0] = pkbf(p00 - bfr(p00), p01 - bfr(p01));
                aPl[1] = pkbf(p10 - bfr(p10), p11 - bfr(p11));
                aPl[2] = pkbf(q00 - bfr(q00), q01 - bfr(q01));
                aPl[3] = pkbf(q10 - bfr(q10), q11 - bfr(q11));
            }
#pragma unroll
            for (int nt = 0; nt < 8; nt++) {
                const int rb = (nt * 8 + gid) * QSTR + kb + tc;
                uint32_t bH0 = Vh[rb], bH1 = Vh[rb + 4];
                uint32_t bL0 = Vl[rb], bL1 = Vl[rb + 4];
                mma16816(accO[nt], aPh, bH0, bH1);
                mma16816(accO[nt], aPh, bL0, bL1);
                mma16816(accO[nt], aPl, bH0, bH1);
            }
        }
    }

    // ---- write partials (unnormalized O + row stats) ----
    const size_t zu = (size_t)b * NU2 + z;
#pragma unroll
    for (int nt = 0; nt < 8; nt++) {
        const int col = nt * 8 + tc * 2;
        *(float2*)&gOp[(zu * 128 + rslab) * 64 + col] =
            make_float2(accO[nt][0], accO[nt][1]);
        *(float2*)&gOp[(zu * 128 + rslab + 8) * 64 + col] =
            make_float2(accO[nt][2], accO[nt][3]);
    }
    if (tc == 0) {
        gMp[zu * 128 + rslab]     = mrun[0];
        gLp[zu * 128 + rslab]     = lrun[0];
        gMp[zu * 128 + rslab + 8] = mrun[1];
        gLp[zu * 128 + rslab + 8] = lrun[1];
    }
}

// ---------------------------------------------------------------------------
// Kernel 3: combine split-KV partials -> out [B,T,H]
// ---------------------------------------------------------------------------
__global__ __launch_bounds__(256)
void combine(float* __restrict__ out)
{
    const int I = blockIdx.x;
    const int b = blockIdx.y;
    int cum = 0;
    for (int m = 0; m < I; m++) cum += (m + 4) >> 2;
    const int nu = (I + 4) >> 2;
    const int r  = threadIdx.x >> 1;
    const int hb = (threadIdx.x & 1) * 32;
    const size_t ub = (size_t)b * NU2 + cum;

    float mmax = -1e30f;
    for (int u = 0; u < nu; u++)
        mmax = fmaxf(mmax, gMp[(ub + u) * 128 + r]);

    float acc[32];
#pragma unroll
    for (int t = 0; t < 32; t++) acc[t] = 0.f;
    float L = 0.f;

    for (int u = 0; u < nu; u++) {
        const float w = __expf(gMp[(ub + u) * 128 + r] - mmax);
        L += w * gLp[(ub + u) * 128 + r];
        const float4* src = (const float4*)&gOp[((ub + u) * 128 + r) * 64 + hb];
#pragma unroll
        for (int t = 0; t < 8; t++) {
            float4 s = src[t];
            acc[t * 4 + 0] += w * s.x;
            acc[t * 4 + 1] += w * s.y;
            acc[t * 4 + 2] += w * s.z;
            acc[t * 4 + 3] += w * s.w;
        }
    }

    const float inv = 1.f / L;
    float4* dst = (float4*)&out[((size_t)(b * TT + I * 128 + r)) * HH + hb];
#pragma unroll
    for (int t = 0; t < 8; t++)
        dst[t] = make_float4(acc[t * 4 + 0] * inv, acc[t * 4 + 1] * inv,
                             acc[t * 4 + 2] * inv, acc[t * 4 + 3] * inv);
}

// ---------------------------------------------------------------------------
extern "C" void kernel_launch(void* const* d_in, const int* in_sizes, int n_in,
                              void* d_out, int out_size)
{
    (void)in_sizes; (void)n_in; (void)out_size;
    const float* x  = (const float*)d_in[0];
    const float* Wq = (const float*)d_in[1];
    const float* Wk = (const float*)d_in[2];
    const float* Wv = (const float*)d_in[3];
    float* out = (float*)d_out;

    const int qkv_smem  = QK_SMEM_U32 * 4;   // 73728 B
    const int attn_smem = AT_SMEM_U32 * 4;   // 73728 B
    static int attr_done = 0;
    if (!attr_done) {
        cudaFuncSetAttribute(qkv_mma, cudaFuncAttributeMaxDynamicSharedMemorySize,
                             qkv_smem);
        cudaFuncSetAttribute(attn_mma, cudaFuncAttributeMaxDynamicSharedMemorySize,
                             attn_smem);
        attr_done = 1;
    }

    qkv_mma<<<(BB * TT) / 64, 256, qkv_smem>>>(x, Wq, Wk, Wv);
    attn_mma<<<dim3(NU2, BB), 256, attn_smem>>>();
    combine<<<dim3(TT / 128, BB), 256>>>(out);
}